// round 15
// baseline (speedup 1.0000x reference)
#include <cuda_runtime.h>
#include <cuda_fp16.h>
#include <cstdint>
#include <cstddef>

#define VOCAB 10000
#define EMBD  100
#define SEQ   80
#define BATCH 1024
#define UNITS 1024

// ---------------- static device scratch (no allocations allowed) ----------------
__device__ float   EP_g[(size_t)VOCAB * UNITS];             // emb@W0x + b0
__device__ __half  H0_g[2][(size_t)BATCH * UNITS];          // h0 fp16 ping-pong
__device__ __half  H1_g[2][(size_t)BATCH * UNITS];          // h1 fp16 ping-pong (2-step delayed)
__device__ float   PB_g[2][(size_t)BATCH * UNITS];          // fp32 partial h0@W1x ping-pong
__device__ __half  W0h_h[(size_t)UNITS * UNITS];            // fp16 k-major
__device__ __half  W1x_h[(size_t)UNITS * UNITS];            // fp16 k-major
__device__ __half  W1h_h[(size_t)UNITS * UNITS];            // fp16 k-major

__device__ __forceinline__ uint32_t smem_u32(const void* p) {
    return (uint32_t)__cvta_generic_to_shared(p);
}

// ---------------- fused prep: zero initial state + convert weights to fp16 ----------------
__global__ void prep_all(const float* __restrict__ W0h,
                         const float* __restrict__ W1x, const float* __restrict__ W1h) {
    const int nthr = gridDim.x * blockDim.x;
    const int tid  = blockIdx.x * blockDim.x + threadIdx.x;
    {
        const size_t n = (size_t)BATCH * UNITS / 8;     // per buffer, uint4 strides
        uint4 z = make_uint4(0, 0, 0, 0);
        uint4* p0 = (uint4*)&H0_g[1][0];                // h0_{-1} (read by TA/TB at t=0)
        uint4* p1 = (uint4*)&H1_g[0][0];                // harmless (guarded reads)
        for (size_t i = tid; i < n; i += nthr) { p0[i] = z; p1[i] = z; }
    }
    for (int i = tid; i < UNITS * UNITS; i += nthr) {
        W0h_h[i] = __float2half_rn(W0h[i]);
        W1x_h[i] = __float2half_rn(W1x[i]);
        W1h_h[i] = __float2half_rn(W1h[i]);
    }
}

// ---------------- EP = emb @ W0x + b0  (fp32, M=10000, K=100, N=1024) ----------------
__global__ void __launch_bounds__(256) ep_kernel(const float* __restrict__ emb,
                                                 const float* __restrict__ W0x,
                                                 const float* __restrict__ b0) {
    __shared__ float se[32][EMBD];
    const int rowbase = blockIdx.y * 32;
    const int colbase = blockIdx.x * 128;
    for (int i = threadIdx.x; i < 32 * EMBD; i += 256) {
        int r = i / EMBD, c = i % EMBD;
        int gr = rowbase + r;
        se[r][c] = (gr < VOCAB) ? emb[(size_t)gr * EMBD + c] : 0.f;
    }
    __syncthreads();
    const int ct = threadIdx.x & 31;
    const int rt = threadIdx.x >> 5;
    const int col = colbase + ct * 4;
    float acc[4][4] = {};
    for (int k = 0; k < EMBD; k++) {
        float4 wv = *(const float4*)&W0x[(size_t)k * UNITS + col];
        #pragma unroll
        for (int i = 0; i < 4; i++) {
            float av = se[rt * 4 + i][k];
            acc[i][0] += av * wv.x; acc[i][1] += av * wv.y;
            acc[i][2] += av * wv.z; acc[i][3] += av * wv.w;
        }
    }
    float4 bv = *(const float4*)&b0[col];
    #pragma unroll
    for (int i = 0; i < 4; i++) {
        int gr = rowbase + rt * 4 + i;
        if (gr < VOCAB) {
            float4 o = make_float4(acc[i][0] + bv.x, acc[i][1] + bv.y,
                                   acc[i][2] + bv.z, acc[i][3] + bv.w);
            *(float4*)&EP_g[(size_t)gr * UNITS + col] = o;
        }
    }
}

// ---------------- GEMM core: 2-group intra-CTA split-K, CTA tile 64x128, K=1024 ----------------
// CTA 256 threads = 2 groups x 4 warps (2m x 2n), warp tile 32x64, BK=64.
// A [*][1024] row-major; B [1024][1024] k-major.
// Returns with group 0 holding the fully reduced accumulators.
#define BM 64
#define BN 128
#define BK 64
#define KT 16

#define APITCH 72                        // 64 + 8 halfs pad (144 B rows)
#define BPITCH 136                       // 128 + 8 halfs pad (272 B rows)
#define AS_STAGE (BM * APITCH)           // 4608 halfs
#define BS_STAGE (BK * BPITCH)           // 8704 halfs
#define STAGE_HALFS (AS_STAGE + BS_STAGE)
#define NSTAGE 4
#define SMEM_BYTES (NSTAGE * STAGE_HALFS * 2)   // 106496 B -> 2 CTAs/SM

__device__ __forceinline__ void gemm_core(const __half* __restrict__ Ag,
                                          const __half* __restrict__ Bg,
                                          int bm, int bn, float acc[2][8][4]) {
    extern __shared__ __align__(16) __half sm[];
    const int tid  = threadIdx.x;
    const int lane = tid & 31;
    const int wid  = tid >> 5;
    const int grp  = wid >> 2;
    const int gtid = tid & 127;
    const int gw   = wid & 3;
    const int wm   = gw >> 1;           // 2 warp rows (32 each)
    const int wn   = gw & 1;            // 2 warp cols (64 each)

    auto gbar = [&]() {
        asm volatile("bar.sync %0, 128;" :: "r"(grp + 1) : "memory");
    };

    auto issue = [&](int kb, int s) {
        __half* As = sm + s * STAGE_HALFS;
        __half* Bs = As + AS_STAGE;
        #pragma unroll
        for (int j = 0; j < 4; j++) {
            int idx = j * 128 + gtid;
            int r = idx >> 3, c = idx & 7;
            const __half* src = Ag + (size_t)(bm + r) * UNITS + kb * BK + c * 8;
            uint32_t dst = smem_u32(As + r * APITCH + c * 8);
            asm volatile("cp.async.cg.shared.global [%0], [%1], 16;\n" ::"r"(dst), "l"(src));
        }
        #pragma unroll
        for (int j = 0; j < 8; j++) {
            int idx = j * 128 + gtid;
            int r = idx >> 4, c = idx & 15;
            const __half* src = Bg + (size_t)(kb * BK + r) * UNITS + bn + c * 8;
            uint32_t dst = smem_u32(Bs + r * BPITCH + c * 8);
            asm volatile("cp.async.cg.shared.global [%0], [%1], 16;\n" ::"r"(dst), "l"(src));
        }
        asm volatile("cp.async.commit_group;\n");
    };

    auto stage_of = [&](int kb) { return grp * 2 + ((kb >> 1) & 1); };

    issue(grp, stage_of(grp));
    issue(grp + 2, stage_of(grp + 2));

    #pragma unroll
    for (int i = 0; i < 2; i++)
        #pragma unroll
        for (int j = 0; j < 8; j++)
            #pragma unroll
            for (int q = 0; q < 4; q++) acc[i][j][q] = 0.f;

    const int arow = (lane & 15);
    const int acol = (lane >> 4) << 3;

    const int ITERS = KT / 2;
    for (int i = 0; i < ITERS; i++) {
        const int kb = grp + 2 * i;
        if (i == ITERS - 1) asm volatile("cp.async.wait_group 0;\n");
        else                asm volatile("cp.async.wait_group 1;\n");
        gbar();
        const int s = stage_of(kb);
        const __half* As = sm + s * STAGE_HALFS;
        const __half* Bs = As + AS_STAGE;

        #pragma unroll
        for (int ks = 0; ks < 4; ks++) {
            uint32_t a[2][4], bb[4][4];
            #pragma unroll
            for (int mi = 0; mi < 2; mi++) {
                uint32_t addr = smem_u32(As + (wm * 32 + mi * 16 + arow) * APITCH
                                         + ks * 16 + acol);
                asm volatile("ldmatrix.sync.aligned.m8n8.x4.shared.b16 {%0,%1,%2,%3}, [%4];\n"
                             : "=r"(a[mi][0]), "=r"(a[mi][1]),
                               "=r"(a[mi][2]), "=r"(a[mi][3]) : "r"(addr));
            }
            #pragma unroll
            for (int nh = 0; nh < 4; nh++) {
                uint32_t addr = smem_u32(Bs + (ks * 16 + arow) * BPITCH
                                         + wn * 64 + nh * 16 + acol);
                asm volatile("ldmatrix.sync.aligned.m8n8.x4.trans.shared.b16 {%0,%1,%2,%3}, [%4];\n"
                             : "=r"(bb[nh][0]), "=r"(bb[nh][1]),
                               "=r"(bb[nh][2]), "=r"(bb[nh][3]) : "r"(addr));
            }
            #pragma unroll
            for (int mi = 0; mi < 2; mi++)
                #pragma unroll
                for (int nn = 0; nn < 8; nn++) {
                    uint32_t b0r = bb[nn >> 1][(nn & 1) * 2];
                    uint32_t b1r = bb[nn >> 1][(nn & 1) * 2 + 1];
                    float* c = acc[mi][nn];
                    asm volatile(
                        "mma.sync.aligned.m16n8k16.row.col.f32.f16.f16.f32 "
                        "{%0,%1,%2,%3}, {%4,%5,%6,%7}, {%8,%9}, {%0,%1,%2,%3};\n"
                        : "+f"(c[0]), "+f"(c[1]), "+f"(c[2]), "+f"(c[3])
                        : "r"(a[mi][0]), "r"(a[mi][1]),
                          "r"(a[mi][2]), "r"(a[mi][3]),
                          "r"(b0r), "r"(b1r));
                }
        }
        gbar();
        if (kb + 4 < KT) issue(kb + 4, stage_of(kb + 4));
    }

    // cross-group reduction: group1 -> smem -> group0
    float* smf = (float*)sm;
    __syncthreads();
    if (grp == 1) {
        #pragma unroll
        for (int mi = 0; mi < 2; mi++)
            #pragma unroll
            for (int nn = 0; nn < 8; nn++)
                #pragma unroll
                for (int q = 0; q < 4; q++)
                    smf[(mi * 32 + nn * 4 + q) * 128 + gtid] = acc[mi][nn][q];
    }
    __syncthreads();
    if (grp == 0) {
        #pragma unroll
        for (int mi = 0; mi < 2; mi++)
            #pragma unroll
            for (int nn = 0; nn < 8; nn++)
                #pragma unroll
                for (int q = 0; q < 4; q++)
                    acc[mi][nn][q] += smf[(mi * 32 + nn * 4 + q) * 128 + gtid];
    }
}

// ---------------- one launch per step: three balanced K=1024 GEMMs ----------------
// z=2 TA: h0_t    = tanh(EP[x[b,t]] + h0_{t-1}@W0h)            -> H0_g[t&1]
// z=1 TB: PB_t    = h0_{t-1}@W1x  (fp32, no activation)        -> PB_g[t&1]
// z=0 TC: h1_{t-2}= tanh(PB_{t-1} + h1_{t-3}@W1h + b1)         -> H1_g[t&1]
//         (t<2: writes exact zeros — true initial states h1_{-2}, h1_{-1})
// Reads: h0_{t-1}=H0_g[(t+1)&1], h1_{t-3}=H1_g[(t+1)&1], PB_{t-1}=PB_g[(t+1)&1]
__global__ void __launch_bounds__(256, 2) rnn_step(int t, const int* __restrict__ xids,
                                                   const float* __restrict__ b1vec) {
    const int z  = blockIdx.z;
    const int bm = blockIdx.y * BM;
    const int bn = blockIdx.x * BN;

    const __half* Ag;
    const __half* Bg;
    if (z == 2)      { Ag = &H0_g[(t + 1) & 1][0]; Bg = W0h_h; }
    else if (z == 1) { Ag = &H0_g[(t + 1) & 1][0]; Bg = W1x_h; }
    else             { Ag = &H1_g[(t + 1) & 1][0]; Bg = W1h_h; }

    float acc[2][8][4];
    gemm_core(Ag, Bg, bm, bn, acc);

    const int tid = threadIdx.x, lane = tid & 31, wid = tid >> 5;
    if ((wid >> 2) != 0) return;                // group 0 only
    const int gw = wid & 3, wm = gw >> 1, wn = gw & 1;
    const int r0 = lane >> 2, cp = lane & 3;

    #pragma unroll
    for (int mi = 0; mi < 2; mi++) {
        #pragma unroll
        for (int rr = 0; rr < 2; rr++) {
            const int b = bm + wm * 32 + mi * 16 + r0 + rr * 8;
            if (z == 2) {
                int xi = xids[b * SEQ + t];
                const float* ep = EP_g + (size_t)xi * UNITS;
                __half* dst = &H0_g[t & 1][(size_t)b * UNITS];
                #pragma unroll
                for (int nn = 0; nn < 8; nn++) {
                    const int u = bn + wn * 64 + nn * 8 + cp * 2;
                    float v0 = tanhf(acc[mi][nn][rr * 2 + 0] + ep[u]);
                    float v1 = tanhf(acc[mi][nn][rr * 2 + 1] + ep[u + 1]);
                    *(__half2*)&dst[u] = __floats2half2_rn(v0, v1);
                }
            } else if (z == 1) {
                float* dst = &PB_g[t & 1][(size_t)b * UNITS];
                #pragma unroll
                for (int nn = 0; nn < 8; nn++) {
                    const int u = bn + wn * 64 + nn * 8 + cp * 2;
                    *(float2*)&dst[u] =
                        make_float2(acc[mi][nn][rr * 2 + 0], acc[mi][nn][rr * 2 + 1]);
                }
            } else {
                const float* pb = &PB_g[(t + 1) & 1][(size_t)b * UNITS];
                __half* dst = &H1_g[t & 1][(size_t)b * UNITS];
                #pragma unroll
                for (int nn = 0; nn < 8; nn++) {
                    const int u = bn + wn * 64 + nn * 8 + cp * 2;
                    float2 pv = *(const float2*)&pb[u];
                    float v0 = tanhf(acc[mi][nn][rr * 2 + 0] + pv.x + b1vec[u]);
                    float v1 = tanhf(acc[mi][nn][rr * 2 + 1] + pv.y + b1vec[u + 1]);
                    if (t < 2) { v0 = 0.f; v1 = 0.f; }      // true initial h1 states
                    *(__half2*)&dst[u] = __floats2half2_rn(v0, v1);
                }
            }
        }
    }
}

// ---------------- output: sigmoid(h1 @ Wout + bout) ----------------
__global__ void out_kernel(const float* __restrict__ Wout, const float* __restrict__ bout,
                           float* __restrict__ out) {
    const int b = blockIdx.x;
    const __half* h1 = &H1_g[1][(size_t)b * UNITS];     // h1_{SEQ-1} written at t=SEQ+1 (odd)
    float s = 0.f;
    for (int u = threadIdx.x; u < UNITS; u += blockDim.x)
        s += __half2float(h1[u]) * Wout[u];
    #pragma unroll
    for (int o = 16; o; o >>= 1) s += __shfl_xor_sync(0xffffffff, s, o);
    __shared__ float red[4];
    if ((threadIdx.x & 31) == 0) red[threadIdx.x >> 5] = s;
    __syncthreads();
    if (threadIdx.x == 0) {
        float tot = red[0] + red[1] + red[2] + red[3] + bout[0];
        out[b] = 1.f / (1.f + expf(-tot));
    }
}

// ---------------- launcher ----------------
extern "C" void kernel_launch(void* const* d_in, const int* in_sizes, int n_in,
                              void* d_out, int out_size) {
    (void)in_sizes; (void)n_in; (void)out_size;
    const int*   x    = (const int*)d_in[0];
    const float* emb  = (const float*)d_in[1];
    const float* W0x  = (const float*)d_in[2];
    const float* W0h  = (const float*)d_in[3];
    const float* b0   = (const float*)d_in[4];
    const float* W1x  = (const float*)d_in[5];
    const float* W1h  = (const float*)d_in[6];
    const float* b1   = (const float*)d_in[7];
    const float* Wout = (const float*)d_in[8];
    const float* bout = (const float*)d_in[9];
    float* out = (float*)d_out;

    cudaFuncSetAttribute(rnn_step, cudaFuncAttributeMaxDynamicSharedMemorySize, SMEM_BYTES);

    prep_all<<<1184, 256>>>(W0h, W1x, W1h);
    ep_kernel<<<dim3(UNITS / 128, (VOCAB + 31) / 32), 256>>>(emb, W0x, b0);

    dim3 gridS(UNITS / BN, BATCH / BM, 3);   // TA+TB+TC: 384 equal CTAs
    dim3 gridB(UNITS / BN, BATCH / BM, 2);   // t=SEQ: TB+TC
    dim3 gridC(UNITS / BN, BATCH / BM, 1);   // t=SEQ+1: TC only
    for (int t = 0; t < SEQ; t++)
        rnn_step<<<gridS, 256, SMEM_BYTES>>>(t, x, b1);
    rnn_step<<<gridB, 256, SMEM_BYTES>>>(SEQ, x, b1);
    rnn_step<<<gridC, 256, SMEM_BYTES>>>(SEQ + 1, x, b1);

    out_kernel<<<BATCH, 128>>>(Wout, bout, out);
}

// round 16
// speedup vs baseline: 1.0648x; 1.0648x over previous
#include <cuda_runtime.h>
#include <cuda_fp16.h>
#include <cstdint>
#include <cstddef>

#define VOCAB 10000
#define EMBD  100
#define SEQ   80
#define BATCH 1024
#define UNITS 1024

// ---------------- static device scratch (no allocations allowed) ----------------
__device__ float   EP_g[(size_t)VOCAB * UNITS];             // emb@W0x + b0
__device__ __half  H0_g[2][(size_t)BATCH * UNITS];          // h0 fp16 ping-pong
__device__ __half  H1_g[2][(size_t)BATCH * UNITS];          // h1 fp16 ping-pong (2-step delayed)
__device__ float   PB_g[2][(size_t)BATCH * UNITS];          // fp32 partial h0@W1x ping-pong
__device__ __half  W0h_h[(size_t)UNITS * UNITS];            // fp16 k-major
__device__ __half  W1x_h[(size_t)UNITS * UNITS];            // fp16 k-major
__device__ __half  W1h_h[(size_t)UNITS * UNITS];            // fp16 k-major

__device__ __forceinline__ uint32_t smem_u32(const void* p) {
    return (uint32_t)__cvta_generic_to_shared(p);
}

// ---------------- fused prep: zero initial state + convert weights to fp16 ----------------
__global__ void prep_all(const float* __restrict__ W0h,
                         const float* __restrict__ W1x, const float* __restrict__ W1h) {
    const int nthr = gridDim.x * blockDim.x;
    const int tid  = blockIdx.x * blockDim.x + threadIdx.x;
    {
        const size_t n = (size_t)BATCH * UNITS / 8;     // per buffer, uint4 strides
        uint4 z = make_uint4(0, 0, 0, 0);
        uint4* p0 = (uint4*)&H0_g[1][0];                // h0_{-1} (read by TA/TB at t=0)
        uint4* p1 = (uint4*)&H1_g[0][0];                // harmless (guarded reads)
        for (size_t i = tid; i < n; i += nthr) { p0[i] = z; p1[i] = z; }
    }
    for (int i = tid; i < UNITS * UNITS; i += nthr) {
        W0h_h[i] = __float2half_rn(W0h[i]);
        W1x_h[i] = __float2half_rn(W1x[i]);
        W1h_h[i] = __float2half_rn(W1h[i]);
    }
}

// ---------------- EP = emb @ W0x + b0  (fp32, M=10000, K=100, N=1024) ----------------
__global__ void __launch_bounds__(256) ep_kernel(const float* __restrict__ emb,
                                                 const float* __restrict__ W0x,
                                                 const float* __restrict__ b0) {
    __shared__ float se[32][EMBD];
    const int rowbase = blockIdx.y * 32;
    const int colbase = blockIdx.x * 128;
    for (int i = threadIdx.x; i < 32 * EMBD; i += 256) {
        int r = i / EMBD, c = i % EMBD;
        int gr = rowbase + r;
        se[r][c] = (gr < VOCAB) ? emb[(size_t)gr * EMBD + c] : 0.f;
    }
    __syncthreads();
    const int ct = threadIdx.x & 31;
    const int rt = threadIdx.x >> 5;
    const int col = colbase + ct * 4;
    float acc[4][4] = {};
    for (int k = 0; k < EMBD; k++) {
        float4 wv = *(const float4*)&W0x[(size_t)k * UNITS + col];
        #pragma unroll
        for (int i = 0; i < 4; i++) {
            float av = se[rt * 4 + i][k];
            acc[i][0] += av * wv.x; acc[i][1] += av * wv.y;
            acc[i][2] += av * wv.z; acc[i][3] += av * wv.w;
        }
    }
    float4 bv = *(const float4*)&b0[col];
    #pragma unroll
    for (int i = 0; i < 4; i++) {
        int gr = rowbase + rt * 4 + i;
        if (gr < VOCAB) {
            float4 o = make_float4(acc[i][0] + bv.x, acc[i][1] + bv.y,
                                   acc[i][2] + bv.z, acc[i][3] + bv.w);
            *(float4*)&EP_g[(size_t)gr * UNITS + col] = o;
        }
    }
}

// ---------------- GEMM core: 128 threads, CTA tile 64x128, K=1024, 2-stage ring ----------------
// 4 warps (2m x 2n), warp tile 32x64. A [*][1024] row-major; B [1024][1024] k-major.
// All warps hold final accumulators for their disjoint 32x64 outputs.
#define BM 64
#define BN 128
#define BK 64
#define KT 16

#define APITCH 72                        // 64 + 8 halfs pad (144 B rows)
#define BPITCH 136                       // 128 + 8 halfs pad (272 B rows)
#define AS_STAGE (BM * APITCH)           // 4608 halfs
#define BS_STAGE (BK * BPITCH)           // 8704 halfs
#define STAGE_HALFS (AS_STAGE + BS_STAGE)
#define NSTAGE 2
#define SMEM_BYTES (NSTAGE * STAGE_HALFS * 2)   // 53248 B -> 4 CTAs/SM

__device__ __forceinline__ void gemm_core(const __half* __restrict__ Ag,
                                          const __half* __restrict__ Bg,
                                          int bm, int bn, float acc[2][8][4]) {
    extern __shared__ __align__(16) __half sm[];
    const int tid  = threadIdx.x;        // 0..127
    const int lane = tid & 31;
    const int wid  = tid >> 5;           // 0..3
    const int wm   = wid >> 1;           // 2 warp rows (32 each)
    const int wn   = wid & 1;            // 2 warp cols (64 each)

    auto issue = [&](int kb, int s) {
        __half* As = sm + s * STAGE_HALFS;
        __half* Bs = As + AS_STAGE;
        // A tile 64x64 halfs = 512 16B chunks, 4 per thread
        #pragma unroll
        for (int j = 0; j < 4; j++) {
            int idx = j * 128 + tid;
            int r = idx >> 3, c = idx & 7;
            const __half* src = Ag + (size_t)(bm + r) * UNITS + kb * BK + c * 8;
            uint32_t dst = smem_u32(As + r * APITCH + c * 8);
            asm volatile("cp.async.cg.shared.global [%0], [%1], 16;\n" ::"r"(dst), "l"(src));
        }
        // B tile 64x128 halfs = 1024 16B chunks, 8 per thread
        #pragma unroll
        for (int j = 0; j < 8; j++) {
            int idx = j * 128 + tid;
            int r = idx >> 4, c = idx & 15;
            const __half* src = Bg + (size_t)(kb * BK + r) * UNITS + bn + c * 8;
            uint32_t dst = smem_u32(Bs + r * BPITCH + c * 8);
            asm volatile("cp.async.cg.shared.global [%0], [%1], 16;\n" ::"r"(dst), "l"(src));
        }
        asm volatile("cp.async.commit_group;\n");
    };

    issue(0, 0);
    issue(1, 1);

    #pragma unroll
    for (int i = 0; i < 2; i++)
        #pragma unroll
        for (int j = 0; j < 8; j++)
            #pragma unroll
            for (int q = 0; q < 4; q++) acc[i][j][q] = 0.f;

    const int arow = (lane & 15);
    const int acol = (lane >> 4) << 3;

    for (int kb = 0; kb < KT; kb++) {
        if (kb == KT - 1) asm volatile("cp.async.wait_group 0;\n");
        else              asm volatile("cp.async.wait_group 1;\n");
        __syncthreads();
        const int s = kb & 1;
        const __half* As = sm + s * STAGE_HALFS;
        const __half* Bs = As + AS_STAGE;

        #pragma unroll
        for (int ks = 0; ks < 4; ks++) {
            uint32_t a[2][4], bb[4][4];
            #pragma unroll
            for (int mi = 0; mi < 2; mi++) {
                uint32_t addr = smem_u32(As + (wm * 32 + mi * 16 + arow) * APITCH
                                         + ks * 16 + acol);
                asm volatile("ldmatrix.sync.aligned.m8n8.x4.shared.b16 {%0,%1,%2,%3}, [%4];\n"
                             : "=r"(a[mi][0]), "=r"(a[mi][1]),
                               "=r"(a[mi][2]), "=r"(a[mi][3]) : "r"(addr));
            }
            #pragma unroll
            for (int nh = 0; nh < 4; nh++) {
                uint32_t addr = smem_u32(Bs + (ks * 16 + arow) * BPITCH
                                         + wn * 64 + nh * 16 + acol);
                asm volatile("ldmatrix.sync.aligned.m8n8.x4.trans.shared.b16 {%0,%1,%2,%3}, [%4];\n"
                             : "=r"(bb[nh][0]), "=r"(bb[nh][1]),
                               "=r"(bb[nh][2]), "=r"(bb[nh][3]) : "r"(addr));
            }
            #pragma unroll
            for (int mi = 0; mi < 2; mi++)
                #pragma unroll
                for (int nn = 0; nn < 8; nn++) {
                    uint32_t b0r = bb[nn >> 1][(nn & 1) * 2];
                    uint32_t b1r = bb[nn >> 1][(nn & 1) * 2 + 1];
                    float* c = acc[mi][nn];
                    asm volatile(
                        "mma.sync.aligned.m16n8k16.row.col.f32.f16.f16.f32 "
                        "{%0,%1,%2,%3}, {%4,%5,%6,%7}, {%8,%9}, {%0,%1,%2,%3};\n"
                        : "+f"(c[0]), "+f"(c[1]), "+f"(c[2]), "+f"(c[3])
                        : "r"(a[mi][0]), "r"(a[mi][1]),
                          "r"(a[mi][2]), "r"(a[mi][3]),
                          "r"(b0r), "r"(b1r));
                }
        }
        __syncthreads();
        if (kb + 2 < KT) issue(kb + 2, s);
    }
}

// ---------------- one launch per step: three balanced K=1024 GEMMs ----------------
// z=2 TA: h0_t    = tanh(EP[x[b,t]] + h0_{t-1}@W0h)            -> H0_g[t&1]
// z=1 TB: PB_t    = h0_{t-1}@W1x  (fp32, no activation)        -> PB_g[t&1]
// z=0 TC: h1_{t-2}= tanh(PB_{t-1} + h1_{t-3}@W1h + b1)         -> H1_g[t&1]
//         (t<2: writes exact zeros — true initial states h1_{-2}, h1_{-1})
// Reads: h0_{t-1}=H0_g[(t+1)&1], h1_{t-3}=H1_g[(t+1)&1], PB_{t-1}=PB_g[(t+1)&1]
__global__ void __launch_bounds__(128, 4) rnn_step(int t, const int* __restrict__ xids,
                                                   const float* __restrict__ b1vec) {
    const int z  = blockIdx.z;
    const int bm = blockIdx.y * BM;
    const int bn = blockIdx.x * BN;

    const __half* Ag;
    const __half* Bg;
    if (z == 2)      { Ag = &H0_g[(t + 1) & 1][0]; Bg = W0h_h; }
    else if (z == 1) { Ag = &H0_g[(t + 1) & 1][0]; Bg = W1x_h; }
    else             { Ag = &H1_g[(t + 1) & 1][0]; Bg = W1h_h; }

    float acc[2][8][4];
    gemm_core(Ag, Bg, bm, bn, acc);

    const int tid = threadIdx.x, lane = tid & 31, wid = tid >> 5;
    const int wm = wid >> 1, wn = wid & 1;
    const int r0 = lane >> 2, cp = lane & 3;

    #pragma unroll
    for (int mi = 0; mi < 2; mi++) {
        #pragma unroll
        for (int rr = 0; rr < 2; rr++) {
            const int b = bm + wm * 32 + mi * 16 + r0 + rr * 8;
            if (z == 2) {
                int xi = xids[b * SEQ + t];
                const float* ep = EP_g + (size_t)xi * UNITS;
                __half* dst = &H0_g[t & 1][(size_t)b * UNITS];
                #pragma unroll
                for (int nn = 0; nn < 8; nn++) {
                    const int u = bn + wn * 64 + nn * 8 + cp * 2;
                    float v0 = tanhf(acc[mi][nn][rr * 2 + 0] + ep[u]);
                    float v1 = tanhf(acc[mi][nn][rr * 2 + 1] + ep[u + 1]);
                    *(__half2*)&dst[u] = __floats2half2_rn(v0, v1);
                }
            } else if (z == 1) {
                float* dst = &PB_g[t & 1][(size_t)b * UNITS];
                #pragma unroll
                for (int nn = 0; nn < 8; nn++) {
                    const int u = bn + wn * 64 + nn * 8 + cp * 2;
                    *(float2*)&dst[u] =
                        make_float2(acc[mi][nn][rr * 2 + 0], acc[mi][nn][rr * 2 + 1]);
                }
            } else {
                const float* pb = &PB_g[(t + 1) & 1][(size_t)b * UNITS];
                __half* dst = &H1_g[t & 1][(size_t)b * UNITS];
                #pragma unroll
                for (int nn = 0; nn < 8; nn++) {
                    const int u = bn + wn * 64 + nn * 8 + cp * 2;
                    float2 pv = *(const float2*)&pb[u];
                    float v0 = tanhf(acc[mi][nn][rr * 2 + 0] + pv.x + b1vec[u]);
                    float v1 = tanhf(acc[mi][nn][rr * 2 + 1] + pv.y + b1vec[u + 1]);
                    if (t < 2) { v0 = 0.f; v1 = 0.f; }      // true initial h1 states
                    *(__half2*)&dst[u] = __floats2half2_rn(v0, v1);
                }
            }
        }
    }
}

// ---------------- output: sigmoid(h1 @ Wout + bout) ----------------
__global__ void out_kernel(const float* __restrict__ Wout, const float* __restrict__ bout,
                           float* __restrict__ out) {
    const int b = blockIdx.x;
    const __half* h1 = &H1_g[1][(size_t)b * UNITS];     // h1_{SEQ-1} written at t=SEQ+1 (odd)
    float s = 0.f;
    for (int u = threadIdx.x; u < UNITS; u += blockDim.x)
        s += __half2float(h1[u]) * Wout[u];
    #pragma unroll
    for (int o = 16; o; o >>= 1) s += __shfl_xor_sync(0xffffffff, s, o);
    __shared__ float red[4];
    if ((threadIdx.x & 31) == 0) red[threadIdx.x >> 5] = s;
    __syncthreads();
    if (threadIdx.x == 0) {
        float tot = red[0] + red[1] + red[2] + red[3] + bout[0];
        out[b] = 1.f / (1.f + expf(-tot));
    }
}

// ---------------- launcher ----------------
extern "C" void kernel_launch(void* const* d_in, const int* in_sizes, int n_in,
                              void* d_out, int out_size) {
    (void)in_sizes; (void)n_in; (void)out_size;
    const int*   x    = (const int*)d_in[0];
    const float* emb  = (const float*)d_in[1];
    const float* W0x  = (const float*)d_in[2];
    const float* W0h  = (const float*)d_in[3];
    const float* b0   = (const float*)d_in[4];
    const float* W1x  = (const float*)d_in[5];
    const float* W1h  = (const float*)d_in[6];
    const float* b1   = (const float*)d_in[7];
    const float* Wout = (const float*)d_in[8];
    const float* bout = (const float*)d_in[9];
    float* out = (float*)d_out;

    cudaFuncSetAttribute(rnn_step, cudaFuncAttributeMaxDynamicSharedMemorySize, SMEM_BYTES);

    prep_all<<<1184, 256>>>(W0h, W1x, W1h);
    ep_kernel<<<dim3(UNITS / 128, (VOCAB + 31) / 32), 256>>>(emb, W0x, b0);

    dim3 gridS(UNITS / BN, BATCH / BM, 3);   // TA+TB+TC: 384 equal CTAs, single wave @4/SM
    dim3 gridB(UNITS / BN, BATCH / BM, 2);   // t=SEQ: TB+TC
    dim3 gridC(UNITS / BN, BATCH / BM, 1);   // t=SEQ+1: TC only
    for (int t = 0; t < SEQ; t++)
        rnn_step<<<gridS, 128, SMEM_BYTES>>>(t, x, b1);
    rnn_step<<<gridB, 128, SMEM_BYTES>>>(SEQ, x, b1);
    rnn_step<<<gridC, 128, SMEM_BYTES>>>(SEQ + 1, x, b1);

    out_kernel<<<BATCH, 128>>>(Wout, bout, out);
}